// round 7
// baseline (speedup 1.0000x reference)
#include <cuda_runtime.h>
#include <cuda_bf16.h>
#include <math.h>

#define NTOK   131072
#define NCODE  2048
#define DIM    64
#define BM     128
#define BN     128

// Output layout (tuple flattened):
#define OFF_XOUT   0
#define OFF_COMMIT 8388608
#define OFF_PERP   8388609
#define OFF_NCB    8388610
#define OFF_NSUM   8519682
#define OFF_NCNT   8650754

// ---- device scratch (no allocations allowed) ----
__device__ int   g_idx[NTOK];
__device__ float g_xnorm[NTOK];
__device__ float g_cnorm[NCODE];
__device__ float g_sumb[NCODE * DIM];
__device__ float g_cntb[NCODE];
__device__ float g_commit;
__device__ float g_plog;

typedef unsigned long long u64;

__device__ __forceinline__ void fma2(u64& d, u64 a, u64 b) {
    asm("fma.rn.f32x2 %0, %1, %2, %0;" : "+l"(d) : "l"(a), "l"(b));
}
__device__ __forceinline__ float2 up(u64 v) {
    float2 r; asm("mov.b64 {%0,%1}, %2;" : "=f"(r.x), "=f"(r.y) : "l"(v)); return r;
}

// ---- K0: zero accumulators ----
__global__ void k_zero() {
    int i = blockIdx.x * 256 + threadIdx.x;
    if (i < NCODE * DIM) g_sumb[i] = 0.0f;
    if (i < NCODE)       g_cntb[i] = 0.0f;
    if (i == 0) { g_commit = 0.0f; g_plog = 0.0f; }
}

// ---- K0b: per-code squared norms (rounded squares, then sequential sum) ----
__global__ void k_cnorm(const float* __restrict__ cb) {
    int c = blockIdx.x * 256 + threadIdx.x;
    if (c >= NCODE) return;
    const float4* p = (const float4*)(cb + c * DIM);
    float s = 0.0f;
#pragma unroll
    for (int q = 0; q < 16; q++) {
        float4 v = p[q];
        s = __fadd_rn(s, __fmul_rn(v.x, v.x));
        s = __fadd_rn(s, __fmul_rn(v.y, v.y));
        s = __fadd_rn(s, __fmul_rn(v.z, v.z));
        s = __fadd_rn(s, __fmul_rn(v.w, v.w));
    }
    g_cnorm[c] = s;
}

// ---- K1: distance GEMM + argmin ----
// FFMA2 register-tiled, MOV-free mainloop: both f32x2 operands live in smem
// as 64-bit values (x pre-duplicated, code pairs naturally adjacent).
// Block: 128 tokens x all 2048 codes. 256 threads as 16(tn) x 16(tm),
// each thread 8 tokens x 8 codes. 96KB dynamic smem, 2 blocks/SM.
__global__ void __launch_bounds__(256, 2) k1_argmin(const float* __restrict__ x,
                                                    const float* __restrict__ cb) {
    extern __shared__ float sm[];
    float* xDf = sm;            // [64][128][2]  x duplicated pairs (64 KB)
    float* cT  = sm + 16384;    // [64][128]     code tile transposed (32 KB)

    int tid = threadIdx.x;
    int tn = tid & 15, tm = tid >> 4;
    int m0 = blockIdx.x * BM;

    // Load x tile (duplicated) + per-token ||x||^2 (rounded squares, seq sum)
    {
        int r = tid >> 1, seg = tid & 1;
        const float4* xp = (const float4*)(x + (long)(m0 + r) * DIM + seg * 32);
        float ps = 0.0f;
#pragma unroll
        for (int q = 0; q < 8; q++) {
            float4 v = xp[q];
            int k = seg * 32 + q * 4;
            float2* d0 = (float2*)&xDf[((k + 0) * 128 + r) * 2];
            float2* d1 = (float2*)&xDf[((k + 1) * 128 + r) * 2];
            float2* d2 = (float2*)&xDf[((k + 2) * 128 + r) * 2];
            float2* d3 = (float2*)&xDf[((k + 3) * 128 + r) * 2];
            *d0 = make_float2(v.x, v.x);
            *d1 = make_float2(v.y, v.y);
            *d2 = make_float2(v.z, v.z);
            *d3 = make_float2(v.w, v.w);
            ps = __fadd_rn(ps, __fmul_rn(v.x, v.x));
            ps = __fadd_rn(ps, __fmul_rn(v.y, v.y));
            ps = __fadd_rn(ps, __fmul_rn(v.z, v.z));
            ps = __fadd_rn(ps, __fmul_rn(v.w, v.w));
        }
        float other = __shfl_xor_sync(0xffffffffu, ps, 1);
        float xn = (seg == 0) ? __fadd_rn(ps, other) : __fadd_rn(other, ps);
        if (seg == 0) g_xnorm[m0 + r] = xn;
    }

    float bv[8];
    int   bi[8];
#pragma unroll
    for (int i = 0; i < 8; i++) { bv[i] = 3.4e38f; bi[i] = 0; }

    u64 acc[8][4];
    float xnr[8];
    bool have_xn = false;

    for (int n0 = 0; n0 < NCODE; n0 += BN) {
        __syncthreads();
        {   // load code tile transposed: cT[k][n], codes n0..n0+127, full K
            int r = tid >> 1, seg = tid & 1;
            const float4* cp = (const float4*)(cb + (long)(n0 + r) * DIM + seg * 32);
#pragma unroll
            for (int q = 0; q < 8; q++) {
                float4 v = cp[q];
                int k = seg * 32 + q * 4;
                cT[(k + 0) * 128 + r] = v.x;
                cT[(k + 1) * 128 + r] = v.y;
                cT[(k + 2) * 128 + r] = v.z;
                cT[(k + 3) * 128 + r] = v.w;
            }
        }
        __syncthreads();

        if (!have_xn) {   // after first sync, xD writes visible; cache ||x||^2
#pragma unroll
            for (int i = 0; i < 8; i++) xnr[i] = g_xnorm[m0 + tm * 8 + i];
            have_xn = true;
        }

#pragma unroll
        for (int i = 0; i < 8; i++)
#pragma unroll
            for (int j = 0; j < 4; j++) acc[i][j] = 0ull;

#pragma unroll 4
        for (int k = 0; k < 64; k++) {
            // a: duplicated x pairs for tokens tm*8..tm*8+7 (4 x LDS.128)
            const ulonglong2* ap = (const ulonglong2*)&xDf[(k * 128 + tm * 8) * 2];
            ulonglong2 a01 = ap[0], a23 = ap[1], a45 = ap[2], a67 = ap[3];
            // b: code pairs for codes tn*8..tn*8+7 (2 x LDS.128)
            const ulonglong2* bp = (const ulonglong2*)&cT[k * 128 + tn * 8];
            ulonglong2 b03 = bp[0], b47 = bp[1];
            u64 as[8] = {a01.x, a01.y, a23.x, a23.y, a45.x, a45.y, a67.x, a67.y};
#pragma unroll
            for (int i = 0; i < 8; i++) {
                fma2(acc[i][0], as[i], b03.x);
                fma2(acc[i][1], as[i], b03.y);
                fma2(acc[i][2], as[i], b47.x);
                fma2(acc[i][3], as[i], b47.y);
            }
        }

        // epilogue: score = (||x||^2 - 2*dot) + ||c||^2, reference op order.
        float cn[8];
#pragma unroll
        for (int j = 0; j < 8; j++) cn[j] = __ldg(&g_cnorm[n0 + tn * 8 + j]);
#pragma unroll
        for (int i = 0; i < 8; i++) {
#pragma unroll
            for (int j = 0; j < 4; j++) {
                float2 v = up(acc[i][j]);
                int cidx = n0 + tn * 8 + 2 * j;
                float s0 = __fadd_rn(__fsub_rn(xnr[i], __fmul_rn(2.0f, v.x)), cn[2 * j]);
                float s1 = __fadd_rn(__fsub_rn(xnr[i], __fmul_rn(2.0f, v.y)), cn[2 * j + 1]);
                if (s0 < bv[i]) { bv[i] = s0; bi[i] = cidx; }
                if (s1 < bv[i]) { bv[i] = s1; bi[i] = cidx + 1; }
            }
        }
    }

    // cross-thread reduction over the 16 tn-groups (reuse cT: 2048 fl + 2048 int)
    __syncthreads();
    float* rv = cT;
    int*   ri = (int*)(cT + 16 * 128);
#pragma unroll
    for (int i = 0; i < 8; i++) {
        rv[tn * 128 + tm * 8 + i] = bv[i];
        ri[tn * 128 + tm * 8 + i] = bi[i];
    }
    __syncthreads();
    if (tid < 128) {
        float best = rv[tid];
        int bidx = ri[tid];
#pragma unroll
        for (int t = 1; t < 16; t++) {
            float v = rv[t * 128 + tid];
            int  id = ri[t * 128 + tid];
            if (v < best || (v == best && id < bidx)) { best = v; bidx = id; }
        }
        g_idx[m0 + tid] = bidx;
    }
}

// ---- K2: gather x_d, write x_out = x + (x_d - x) (reference rounding),
//          segment-sum scatter, commit loss. 4 threads per token, 16 dims each.
__global__ void k_scatter(const float* __restrict__ x, const float* __restrict__ cb,
                          float* __restrict__ out) {
    int gt = blockIdx.x * blockDim.x + threadIdx.x;
    int t = gt >> 2, part = gt & 3;
    int idx = g_idx[t];
    const float4* xp = (const float4*)(x + (long)t * DIM + part * 16);
    const float4* cp = (const float4*)(cb + (long)idx * DIM + part * 16);
    float4* op = (float4*)(out + OFF_XOUT + (long)t * DIM + part * 16);
    float* sb = &g_sumb[idx * DIM + part * 16];
    float cs = 0.0f;
#pragma unroll
    for (int q = 0; q < 4; q++) {
        float4 xv = xp[q];
        float4 cv = cp[q];
        float4 o;
        o.x = __fadd_rn(xv.x, __fsub_rn(cv.x, xv.x));
        o.y = __fadd_rn(xv.y, __fsub_rn(cv.y, xv.y));
        o.z = __fadd_rn(xv.z, __fsub_rn(cv.z, xv.z));
        o.w = __fadd_rn(xv.w, __fsub_rn(cv.w, xv.w));
        op[q] = o;
        float dx = __fsub_rn(xv.x, cv.x), dy = __fsub_rn(xv.y, cv.y);
        float dz = __fsub_rn(xv.z, cv.z), dw = __fsub_rn(xv.w, cv.w);
        cs += dx * dx + dy * dy + dz * dz + dw * dw;
        atomicAdd(sb + q * 4 + 0, xv.x);
        atomicAdd(sb + q * 4 + 1, xv.y);
        atomicAdd(sb + q * 4 + 2, xv.z);
        atomicAdd(sb + q * 4 + 3, xv.w);
    }
    if (part == 0) atomicAdd(&g_cntb[idx], 1.0f);
#pragma unroll
    for (int o = 16; o; o >>= 1) cs += __shfl_xor_sync(0xffffffff, cs, o);
    if ((threadIdx.x & 31) == 0) atomicAdd(&g_commit, cs);
}

// ---- K3: EMA update, new codebook, perplexity partials ----
__global__ void k_final(const float* __restrict__ x, const float* __restrict__ code_sum,
                        const float* __restrict__ code_count, float* __restrict__ out) {
    int i = blockIdx.x * 256 + threadIdx.x;   // over NCODE*DIM
    int c = i >> 6, d = i & 63;
    float cntb = g_cntb[c];
    float ncnt = 0.99f * code_count[c] + 0.01f * cntb;
    float ns = 0.99f * code_sum[i] + 0.01f * g_sumb[i];
    out[OFF_NSUM + i] = ns;
    bool used = (ncnt >= 1.0f);
    float refreshed = ns / fmaxf(ncnt, 1e-8f);
    out[OFF_NCB + i] = used ? refreshed : x[i];   // x[:NCODE] flattened == x[i]
    if (d == 0) {
        out[OFF_NCNT + c] = ncnt;
        float p = cntb * (1.0f / 131072.0f);
        atomicAdd(&g_plog, p * logf(p + 1e-7f));
    }
}

// ---- K4: scalars ----
__global__ void k_scalars(float* __restrict__ out) {
    out[OFF_COMMIT] = g_commit * (1.0f / 8388608.0f);
    out[OFF_PERP]   = expf(-g_plog);
}

extern "C" void kernel_launch(void* const* d_in, const int* in_sizes, int n_in,
                              void* d_out, int out_size) {
    const float* x     = (const float*)d_in[0];
    const float* cb    = (const float*)d_in[1];
    const float* csum  = (const float*)d_in[2];
    const float* ccnt  = (const float*)d_in[3];
    float* out = (float*)d_out;

    const int smem_k1 = 96 * 1024;   // 64KB xD + 32KB cT
    cudaFuncSetAttribute(k1_argmin, cudaFuncAttributeMaxDynamicSharedMemorySize, smem_k1);

    k_zero<<<512, 256>>>();
    k_cnorm<<<8, 256>>>(cb);
    k1_argmin<<<NTOK / BM, 256, smem_k1>>>(x, cb);
    k_scatter<<<NTOK * 4 / 256, 256>>>(x, cb, out);
    k_final<<<NCODE * DIM / 256, 256>>>(x, csum, ccnt, out);
    k_scalars<<<1, 1>>>(out);
}

// round 10
// speedup vs baseline: 1.9029x; 1.9029x over previous
#include <cuda_runtime.h>
#include <cuda_fp16.h>
#include <math.h>
#include <stdint.h>

#define NTOK   131072
#define NCODE  2048
#define DIM    64

// Output layout (tuple flattened):
#define OFF_XOUT   0
#define OFF_COMMIT 8388608
#define OFF_PERP   8388609
#define OFF_NCB    8388610
#define OFF_NSUM   8519682
#define OFF_NCNT   8650754

// ---- device scratch ----
__device__ int   g_idx[NTOK];
__device__ float g_xnorm[NTOK];
__device__ float g_cnorm[NCODE];
__device__ float g_sumb[NCODE * DIM];
__device__ float g_cntb[NCODE];
__device__ float g_commit;
__device__ float g_plog;
__device__ __half g_xh[NTOK * DIM];
__device__ __half g_xm[NTOK * DIM];
__device__ __half g_ch[NCODE * DIM];
__device__ __half g_cm[NCODE * DIM];

__device__ __forceinline__ uint32_t smem_u32(const void* p) {
    uint32_t a;
    asm("{ .reg .u64 t; cvta.to.shared.u64 t, %1; cvt.u32.u64 %0, t; }" : "=r"(a) : "l"(p));
    return a;
}
#define LDX4(r, addr) \
    asm volatile("ldmatrix.sync.aligned.m8n8.x4.shared.b16 {%0,%1,%2,%3}, [%4];" \
        : "=r"((r)[0]), "=r"((r)[1]), "=r"((r)[2]), "=r"((r)[3]) : "r"(addr))

__device__ __forceinline__ void mma16816(float* c, const uint32_t* a, uint32_t b0, uint32_t b1) {
    asm volatile("mma.sync.aligned.m16n8k16.row.col.f32.f16.f16.f32 "
        "{%0,%1,%2,%3},{%4,%5,%6,%7},{%8,%9},{%0,%1,%2,%3};"
        : "+f"(c[0]), "+f"(c[1]), "+f"(c[2]), "+f"(c[3])
        : "r"(a[0]), "r"(a[1]), "r"(a[2]), "r"(a[3]), "r"(b0), "r"(b1));
}

union U8H { __half h[8]; uint4 u; };

// ---- K0: zero accumulators ----
__global__ void k_zero() {
    int i = blockIdx.x * 256 + threadIdx.x;
    if (i < NCODE * DIM) g_sumb[i] = 0.0f;
    if (i < NCODE)       g_cntb[i] = 0.0f;
    if (i == 0) { g_commit = 0.0f; g_plog = 0.0f; }
}

// ---- K0a: split x into fp16 pair + ||x||^2 (reference rounding order) ----
__global__ void k_split_x(const float* __restrict__ x) {
    int t = blockIdx.x * 256 + threadIdx.x;
    const float4* xp = (const float4*)(x + (size_t)t * DIM);
    float xn = 0.0f;
#pragma unroll
    for (int q = 0; q < 8; q++) {
        float4 a = xp[2 * q], b = xp[2 * q + 1];
        float v[8] = {a.x, a.y, a.z, a.w, b.x, b.y, b.z, b.w};
        U8H H, M;
#pragma unroll
        for (int i = 0; i < 8; i++) {
            float vi = v[i];
            __half hb = __float2half_rn(vi);
            __half mb = __float2half_rn(__fsub_rn(vi, __half2float(hb)));
            H.h[i] = hb; M.h[i] = mb;
            xn = __fadd_rn(xn, __fmul_rn(vi, vi));
        }
        *(uint4*)&g_xh[(size_t)t * DIM + q * 8] = H.u;
        *(uint4*)&g_xm[(size_t)t * DIM + q * 8] = M.u;
    }
    g_xnorm[t] = xn;
}

// ---- K0b: split codebook + ||c||^2 ----
__global__ void k_split_cb(const float* __restrict__ cb) {
    int c = blockIdx.x * 256 + threadIdx.x;
    if (c >= NCODE) return;
    const float4* cp = (const float4*)(cb + (size_t)c * DIM);
    float cn = 0.0f;
#pragma unroll
    for (int q = 0; q < 8; q++) {
        float4 a = cp[2 * q], b = cp[2 * q + 1];
        float v[8] = {a.x, a.y, a.z, a.w, b.x, b.y, b.z, b.w};
        U8H H, M;
#pragma unroll
        for (int i = 0; i < 8; i++) {
            float vi = v[i];
            __half hb = __float2half_rn(vi);
            __half mb = __float2half_rn(__fsub_rn(vi, __half2float(hb)));
            H.h[i] = hb; M.h[i] = mb;
            cn = __fadd_rn(cn, __fmul_rn(vi, vi));
        }
        *(uint4*)&g_ch[(size_t)c * DIM + q * 8] = H.u;
        *(uint4*)&g_cm[(size_t)c * DIM + q * 8] = M.u;
    }
    g_cnorm[c] = cn;
}

// ---- K1: HMMA fp16-split distance GEMM + fused per-lane argmin ----
// Block = 128 tokens (8 warps x 16). Codes streamed in 16 chunks of 128.
// dot = xh*ch + xh*cm + xm*ch + xm*cm accumulated in fp32 (4 mma per frag pair).
// smem rows padded to 72 halves (144B) -> conflict-free LDSM.
#define SMSTRIDE 72
__global__ void __launch_bounds__(256, 2) k1_hmma() {
    __shared__ __align__(16) __half bufh[128 * SMSTRIDE];
    __shared__ __align__(16) __half bufm[128 * SMSTRIDE];
    __shared__ float cns[128];

    int tid = threadIdx.x, w = tid >> 5, l = tid & 31;
    int g = l >> 3, lr = l & 7, gid = l >> 2, tig = l & 3;
    int m0 = blockIdx.x * 128;

    // stage x (h,m) tiles
    for (int i = tid; i < 1024; i += 256) {
        int r = i >> 3, j = i & 7;
        *(uint4*)&bufh[r * SMSTRIDE + j * 8] = *(const uint4*)&g_xh[(size_t)(m0 + r) * DIM + j * 8];
        *(uint4*)&bufm[r * SMSTRIDE + j * 8] = *(const uint4*)&g_xm[(size_t)(m0 + r) * DIM + j * 8];
    }
    __syncthreads();

    // load A fragments (register-resident for the whole kernel)
    uint32_t ah[4][4], am[4][4];
    {
        int arow = w * 16 + (g & 1) * 8 + lr;
#pragma unroll
        for (int kk = 0; kk < 4; kk++) {
            int acol = kk * 16 + (g >> 1) * 8;
            uint32_t adh = smem_u32(&bufh[arow * SMSTRIDE + acol]);
            uint32_t adm = smem_u32(&bufm[arow * SMSTRIDE + acol]);
            LDX4(ah[kk], adh);
            LDX4(am[kk], adm);
        }
    }
    __syncthreads();

    float xn0 = g_xnorm[m0 + w * 16 + gid];
    float xn1 = g_xnorm[m0 + w * 16 + gid + 8];
    float bv0 = 3.4e38f, bv1 = 3.4e38f;
    int bi0 = 0, bi1 = 0;

    for (int c = 0; c < 16; c++) {
        // stage B chunk (codes c*128 .. +127), h and m, + code norms
        for (int i = tid; i < 1024; i += 256) {
            int r = i >> 3, j = i & 7;
            *(uint4*)&bufh[r * SMSTRIDE + j * 8] = *(const uint4*)&g_ch[(size_t)(c * 128 + r) * DIM + j * 8];
            *(uint4*)&bufm[r * SMSTRIDE + j * 8] = *(const uint4*)&g_cm[(size_t)(c * 128 + r) * DIM + j * 8];
        }
        if (tid < 128) cns[tid] = g_cnorm[c * 128 + tid];
        __syncthreads();

#pragma unroll
        for (int hf = 0; hf < 2; hf++) {
            float acc[8][4];
#pragma unroll
            for (int n = 0; n < 8; n++)
#pragma unroll
                for (int q = 0; q < 4; q++) acc[n][q] = 0.0f;

#pragma unroll
            for (int kk = 0; kk < 4; kk++) {
#pragma unroll
                for (int p = 0; p < 4; p++) {
                    int brow = hf * 64 + p * 16 + (g & 1) * 8 + lr;
                    int bcol = kk * 16 + (g >> 1) * 8;
                    uint32_t bh[4], bm[4];
                    LDX4(bh, smem_u32(&bufh[brow * SMSTRIDE + bcol]));
                    LDX4(bm, smem_u32(&bufm[brow * SMSTRIDE + bcol]));
                    // ntile 2p uses {r0,r2}; ntile 2p+1 uses {r1,r3}
                    mma16816(acc[2 * p],     ah[kk], bh[0], bh[2]);
                    mma16816(acc[2 * p],     ah[kk], bm[0], bm[2]);
                    mma16816(acc[2 * p],     am[kk], bh[0], bh[2]);
                    mma16816(acc[2 * p],     am[kk], bm[0], bm[2]);
                    mma16816(acc[2 * p + 1], ah[kk], bh[1], bh[3]);
                    mma16816(acc[2 * p + 1], ah[kk], bm[1], bm[3]);
                    mma16816(acc[2 * p + 1], am[kk], bh[1], bh[3]);
                    mma16816(acc[2 * p + 1], am[kk], bm[1], bm[3]);
                }
            }
            // epilogue: score = (||x||^2 - 2*dot) + ||c||^2 (reference op order),
            // running strict-< argmin in ascending code order.
#pragma unroll
            for (int nt = 0; nt < 8; nt++) {
                int nl = hf * 64 + nt * 8 + 2 * tig;
                float cn0 = cns[nl], cn1 = cns[nl + 1];
                int ci = c * 128 + nl;
                float s;
                s = __fadd_rn(__fsub_rn(xn0, __fmul_rn(2.0f, acc[nt][0])), cn0);
                if (s < bv0) { bv0 = s; bi0 = ci; }
                s = __fadd_rn(__fsub_rn(xn0, __fmul_rn(2.0f, acc[nt][1])), cn1);
                if (s < bv0) { bv0 = s; bi0 = ci + 1; }
                s = __fadd_rn(__fsub_rn(xn1, __fmul_rn(2.0f, acc[nt][2])), cn0);
                if (s < bv1) { bv1 = s; bi1 = ci; }
                s = __fadd_rn(__fsub_rn(xn1, __fmul_rn(2.0f, acc[nt][3])), cn1);
                if (s < bv1) { bv1 = s; bi1 = ci + 1; }
            }
        }
        __syncthreads();
    }

    // quad (4-lane) reduce, tie -> lower index
#pragma unroll
    for (int off = 1; off <= 2; off <<= 1) {
        float ov0 = __shfl_xor_sync(0xffffffffu, bv0, off);
        int   oi0 = __shfl_xor_sync(0xffffffffu, bi0, off);
        if (ov0 < bv0 || (ov0 == bv0 && oi0 < bi0)) { bv0 = ov0; bi0 = oi0; }
        float ov1 = __shfl_xor_sync(0xffffffffu, bv1, off);
        int   oi1 = __shfl_xor_sync(0xffffffffu, bi1, off);
        if (ov1 < bv1 || (ov1 == bv1 && oi1 < bi1)) { bv1 = ov1; bi1 = oi1; }
    }
    if (tig == 0) {
        g_idx[m0 + w * 16 + gid]     = bi0;
        g_idx[m0 + w * 16 + gid + 8] = bi1;
    }
}

// ---- K2: gather x_d, x_out = x + (x_d - x), segment-sum scatter, commit ----
__global__ void k_scatter(const float* __restrict__ x, const float* __restrict__ cb,
                          float* __restrict__ out) {
    int gt = blockIdx.x * blockDim.x + threadIdx.x;
    int t = gt >> 2, part = gt & 3;
    int idx = g_idx[t];
    const float4* xp = (const float4*)(x + (size_t)t * DIM + part * 16);
    const float4* cp = (const float4*)(cb + (size_t)idx * DIM + part * 16);
    float4* op = (float4*)(out + OFF_XOUT + (size_t)t * DIM + part * 16);
    float* sbm = &g_sumb[idx * DIM + part * 16];
    float cs = 0.0f;
#pragma unroll
    for (int q = 0; q < 4; q++) {
        float4 xv = xp[q];
        float4 cv = cp[q];
        float4 o;
        o.x = __fadd_rn(xv.x, __fsub_rn(cv.x, xv.x));
        o.y = __fadd_rn(xv.y, __fsub_rn(cv.y, xv.y));
        o.z = __fadd_rn(xv.z, __fsub_rn(cv.z, xv.z));
        o.w = __fadd_rn(xv.w, __fsub_rn(cv.w, xv.w));
        op[q] = o;
        float dx = __fsub_rn(xv.x, cv.x), dy = __fsub_rn(xv.y, cv.y);
        float dz = __fsub_rn(xv.z, cv.z), dw = __fsub_rn(xv.w, cv.w);
        cs += dx * dx + dy * dy + dz * dz + dw * dw;
        atomicAdd(sbm + q * 4 + 0, xv.x);
        atomicAdd(sbm + q * 4 + 1, xv.y);
        atomicAdd(sbm + q * 4 + 2, xv.z);
        atomicAdd(sbm + q * 4 + 3, xv.w);
    }
    if (part == 0) atomicAdd(&g_cntb[idx], 1.0f);
#pragma unroll
    for (int o = 16; o; o >>= 1) cs += __shfl_xor_sync(0xffffffff, cs, o);
    if ((threadIdx.x & 31) == 0) atomicAdd(&g_commit, cs);
}

// ---- K3: EMA update, new codebook, perplexity partials ----
__global__ void k_final(const float* __restrict__ x, const float* __restrict__ code_sum,
                        const float* __restrict__ code_count, float* __restrict__ out) {
    int i = blockIdx.x * 256 + threadIdx.x;
    int c = i >> 6, d = i & 63;
    float cntb = g_cntb[c];
    float ncnt = 0.99f * code_count[c] + 0.01f * cntb;
    float ns = 0.99f * code_sum[i] + 0.01f * g_sumb[i];
    out[OFF_NSUM + i] = ns;
    bool used = (ncnt >= 1.0f);
    float refreshed = ns / fmaxf(ncnt, 1e-8f);
    out[OFF_NCB + i] = used ? refreshed : x[i];
    if (d == 0) {
        out[OFF_NCNT + c] = ncnt;
        float p = cntb * (1.0f / 131072.0f);
        atomicAdd(&g_plog, p * logf(p + 1e-7f));
    }
}

// ---- K4: scalars ----
__global__ void k_scalars(float* __restrict__ out) {
    out[OFF_COMMIT] = g_commit * (1.0f / 8388608.0f);
    out[OFF_PERP]   = expf(-g_plog);
}

extern "C" void kernel_launch(void* const* d_in, const int* in_sizes, int n_in,
                              void* d_out, int out_size) {
    const float* x    = (const float*)d_in[0];
    const float* cb   = (const float*)d_in[1];
    const float* csum = (const float*)d_in[2];
    const float* ccnt = (const float*)d_in[3];
    float* out = (float*)d_out;

    k_zero<<<512, 256>>>();
    k_split_x<<<NTOK / 256, 256>>>(x);
    k_split_cb<<<8, 256>>>(cb);
    k1_hmma<<<NTOK / 128, 256>>>();
    k_scatter<<<NTOK * 4 / 256, 256>>>(x, cb, out);
    k_final<<<NCODE * DIM / 256, 256>>>(x, csum, ccnt, out);
    k_scalars<<<1, 1>>>(out);
}

// round 11
// speedup vs baseline: 2.3807x; 1.2511x over previous
#include <cuda_runtime.h>
#include <cuda_fp16.h>
#include <math.h>
#include <stdint.h>

#define NTOK   131072
#define NCODE  2048
#define DIM    64

// Output layout (tuple flattened):
#define OFF_XOUT   0
#define OFF_COMMIT 8388608
#define OFF_PERP   8388609
#define OFF_NCB    8388610
#define OFF_NSUM   8519682
#define OFF_NCNT   8650754

// ---- device scratch ----
__device__ int   g_idx[NTOK];
__device__ float g_xnorm[NTOK];
__device__ float g_cnorm[NCODE];
__device__ float g_sumb[NCODE * DIM];
__device__ float g_cntb[NCODE];
__device__ float g_commit;
__device__ float g_plog;
__device__ __half g_xh[NTOK * DIM];
__device__ __half g_xm[NTOK * DIM];
__device__ __half g_ch[NCODE * DIM];
__device__ __half g_cm[NCODE * DIM];

__device__ __forceinline__ uint32_t smem_u32(const void* p) {
    uint32_t a;
    asm("{ .reg .u64 t; cvta.to.shared.u64 t, %1; cvt.u32.u64 %0, t; }" : "=r"(a) : "l"(p));
    return a;
}
#define LDX4(r, addr) \
    asm volatile("ldmatrix.sync.aligned.m8n8.x4.shared.b16 {%0,%1,%2,%3}, [%4];" \
        : "=r"((r)[0]), "=r"((r)[1]), "=r"((r)[2]), "=r"((r)[3]) : "r"(addr))

__device__ __forceinline__ void mma16816(float* c, const uint32_t* a, uint32_t b0, uint32_t b1) {
    asm volatile("mma.sync.aligned.m16n8k16.row.col.f32.f16.f16.f32 "
        "{%0,%1,%2,%3},{%4,%5,%6,%7},{%8,%9},{%0,%1,%2,%3};"
        : "+f"(c[0]), "+f"(c[1]), "+f"(c[2]), "+f"(c[3])
        : "r"(a[0]), "r"(a[1]), "r"(a[2]), "r"(a[3]), "r"(b0), "r"(b1));
}
__device__ __forceinline__ void cpa16(uint32_t dst, const void* src) {
    asm volatile("cp.async.cg.shared.global [%0], [%1], 16;" :: "r"(dst), "l"(src));
}
#define CPA_COMMIT() asm volatile("cp.async.commit_group;" ::: "memory")
#define CPA_WAIT0()  asm volatile("cp.async.wait_group 0;" ::: "memory")
#define CPA_WAIT1()  asm volatile("cp.async.wait_group 1;" ::: "memory")

union U8H { __half h[8]; uint4 u; };

// smem buffer layout (bytes): bh[128*144] @0, bm[128*144] @18432, cns[128]f @36864
#define BUFB   37376
#define OFF_BM 18432
#define OFF_CN 36864
#define SMEMT  (2 * BUFB)

// ---- K0: zero accumulators ----
__global__ void k_zero() {
    int i = blockIdx.x * 256 + threadIdx.x;
    if (i < NCODE * DIM) g_sumb[i] = 0.0f;
    if (i < NCODE)       g_cntb[i] = 0.0f;
    if (i == 0) { g_commit = 0.0f; g_plog = 0.0f; }
}

// ---- K0a: split x into fp16 pair + ||x||^2 (reference rounding order) ----
__global__ void k_split_x(const float* __restrict__ x) {
    int t = blockIdx.x * 256 + threadIdx.x;
    const float4* xp = (const float4*)(x + (size_t)t * DIM);
    float xn = 0.0f;
#pragma unroll
    for (int q = 0; q < 8; q++) {
        float4 a = xp[2 * q], b = xp[2 * q + 1];
        float v[8] = {a.x, a.y, a.z, a.w, b.x, b.y, b.z, b.w};
        U8H H, M;
#pragma unroll
        for (int i = 0; i < 8; i++) {
            float vi = v[i];
            __half hb = __float2half_rn(vi);
            __half mb = __float2half_rn(__fsub_rn(vi, __half2float(hb)));
            H.h[i] = hb; M.h[i] = mb;
            xn = __fadd_rn(xn, __fmul_rn(vi, vi));
        }
        *(uint4*)&g_xh[(size_t)t * DIM + q * 8] = H.u;
        *(uint4*)&g_xm[(size_t)t * DIM + q * 8] = M.u;
    }
    g_xnorm[t] = xn;
}

// ---- K0b: split codebook + ||c||^2 ----
__global__ void k_split_cb(const float* __restrict__ cb) {
    int c = blockIdx.x * 256 + threadIdx.x;
    if (c >= NCODE) return;
    const float4* cp = (const float4*)(cb + (size_t)c * DIM);
    float cn = 0.0f;
#pragma unroll
    for (int q = 0; q < 8; q++) {
        float4 a = cp[2 * q], b = cp[2 * q + 1];
        float v[8] = {a.x, a.y, a.z, a.w, b.x, b.y, b.z, b.w};
        U8H H, M;
#pragma unroll
        for (int i = 0; i < 8; i++) {
            float vi = v[i];
            __half hb = __float2half_rn(vi);
            __half mb = __float2half_rn(__fsub_rn(vi, __half2float(hb)));
            H.h[i] = hb; M.h[i] = mb;
            cn = __fadd_rn(cn, __fmul_rn(vi, vi));
        }
        *(uint4*)&g_ch[(size_t)c * DIM + q * 8] = H.u;
        *(uint4*)&g_cm[(size_t)c * DIM + q * 8] = M.u;
    }
    g_cnorm[c] = cn;
}

// ---- K1: HMMA fp16-split distance GEMM + fused per-lane argmin ----
// 3 passes (hh, hm, mh; the mm term ~2e-8 is dropped), cp.async double-buffered
// B chunks. Block = 128 tokens (8 warps x 16 rows). 16 chunks of 128 codes.
__device__ __forceinline__ void prefetch_chunk(uint32_t bsm, int n0, int tid) {
#pragma unroll
    for (int i = tid; i < 1024; i += 256) {
        int r = i >> 3, j = i & 7;
        cpa16(bsm + r * 144 + j * 16, &g_ch[(size_t)(n0 + r) * DIM + j * 8]);
        cpa16(bsm + OFF_BM + r * 144 + j * 16, &g_cm[(size_t)(n0 + r) * DIM + j * 8]);
    }
    if (tid < 32) cpa16(bsm + OFF_CN + tid * 16, &g_cnorm[n0 + tid * 4]);
}

__global__ void __launch_bounds__(256, 2) k1_hmma() {
    extern __shared__ __align__(16) char dyn[];
    uint32_t sb = smem_u32(dyn);
    int tid = threadIdx.x, w = tid >> 5, l = tid & 31;
    int g = l >> 3, lr = l & 7, gid = l >> 2, tig = l & 3;
    int m0 = blockIdx.x * 128;

    // stage A (xh, xm) into buf0 via cp.async
    for (int i = tid; i < 1024; i += 256) {
        int r = i >> 3, j = i & 7;
        cpa16(sb + r * 144 + j * 16, &g_xh[(size_t)(m0 + r) * DIM + j * 8]);
        cpa16(sb + OFF_BM + r * 144 + j * 16, &g_xm[(size_t)(m0 + r) * DIM + j * 8]);
    }
    CPA_COMMIT();
    CPA_WAIT0();
    __syncthreads();

    // A fragments register-resident for the whole kernel
    uint32_t ah[4][4], am[4][4];
    {
        int arow = w * 16 + (g & 1) * 8 + lr;
#pragma unroll
        for (int kk = 0; kk < 4; kk++) {
            int acol = kk * 16 + (g >> 1) * 8;
            LDX4(ah[kk], sb + arow * 144 + acol * 2);
            LDX4(am[kk], sb + OFF_BM + arow * 144 + acol * 2);
        }
    }
    __syncthreads();

    float xn0 = g_xnorm[m0 + w * 16 + gid];
    float xn1 = g_xnorm[m0 + w * 16 + gid + 8];
    float bv0 = 3.4e38f, bv1 = 3.4e38f;
    int bi0 = 0, bi1 = 0;

    prefetch_chunk(sb, 0, tid);          CPA_COMMIT();
    prefetch_chunk(sb + BUFB, 128, tid); CPA_COMMIT();

    for (int c = 0; c < 16; c++) {
        uint32_t bb = sb + (c & 1) * BUFB;
        const float* cns = (const float*)(dyn + (c & 1) * BUFB + OFF_CN);
        CPA_WAIT1();
        __syncthreads();

#pragma unroll
        for (int hf = 0; hf < 2; hf++) {
            float acc[8][4];
#pragma unroll
            for (int n = 0; n < 8; n++)
#pragma unroll
                for (int q = 0; q < 4; q++) acc[n][q] = 0.0f;

#pragma unroll
            for (int kk = 0; kk < 4; kk++) {
#pragma unroll
                for (int p = 0; p < 4; p++) {
                    int brow = hf * 64 + p * 16 + (g & 1) * 8 + lr;
                    int bcol = kk * 16 + (g >> 1) * 8;
                    uint32_t bh[4], bm[4];
                    LDX4(bh, bb + brow * 144 + bcol * 2);
                    LDX4(bm, bb + OFF_BM + brow * 144 + bcol * 2);
                    // ntile 2p uses {r0,r2}; ntile 2p+1 uses {r1,r3}
                    mma16816(acc[2 * p],     ah[kk], bh[0], bh[2]);
                    mma16816(acc[2 * p],     ah[kk], bm[0], bm[2]);
                    mma16816(acc[2 * p],     am[kk], bh[0], bh[2]);
                    mma16816(acc[2 * p + 1], ah[kk], bh[1], bh[3]);
                    mma16816(acc[2 * p + 1], ah[kk], bm[1], bm[3]);
                    mma16816(acc[2 * p + 1], am[kk], bh[1], bh[3]);
                }
            }
            // epilogue: score = (||x||^2 - 2*dot) + ||c||^2 (reference op order),
            // running strict-< argmin in ascending code order.
#pragma unroll
            for (int nt = 0; nt < 8; nt++) {
                int nl = hf * 64 + nt * 8 + 2 * tig;
                float cn0 = cns[nl], cn1 = cns[nl + 1];
                int ci = c * 128 + nl;
                float s;
                s = __fadd_rn(__fsub_rn(xn0, __fmul_rn(2.0f, acc[nt][0])), cn0);
                if (s < bv0) { bv0 = s; bi0 = ci; }
                s = __fadd_rn(__fsub_rn(xn0, __fmul_rn(2.0f, acc[nt][1])), cn1);
                if (s < bv0) { bv0 = s; bi0 = ci + 1; }
                s = __fadd_rn(__fsub_rn(xn1, __fmul_rn(2.0f, acc[nt][2])), cn0);
                if (s < bv1) { bv1 = s; bi1 = ci; }
                s = __fadd_rn(__fsub_rn(xn1, __fmul_rn(2.0f, acc[nt][3])), cn1);
                if (s < bv1) { bv1 = s; bi1 = ci + 1; }
            }
        }
        __syncthreads();
        if (c + 2 < 16) prefetch_chunk(bb, (c + 2) * 128, tid);
        CPA_COMMIT();   // always commit (possibly empty) to keep group count in sync
    }

    // quad (4-lane) reduce, tie -> lower index
#pragma unroll
    for (int off = 1; off <= 2; off <<= 1) {
        float ov0 = __shfl_xor_sync(0xffffffffu, bv0, off);
        int   oi0 = __shfl_xor_sync(0xffffffffu, bi0, off);
        if (ov0 < bv0 || (ov0 == bv0 && oi0 < bi0)) { bv0 = ov0; bi0 = oi0; }
        float ov1 = __shfl_xor_sync(0xffffffffu, bv1, off);
        int   oi1 = __shfl_xor_sync(0xffffffffu, bi1, off);
        if (ov1 < bv1 || (ov1 == bv1 && oi1 < bi1)) { bv1 = ov1; bi1 = oi1; }
    }
    if (tig == 0) {
        g_idx[m0 + w * 16 + gid]     = bi0;
        g_idx[m0 + w * 16 + gid + 8] = bi1;
    }
}

// ---- K2: gather x_d, x_out = x + (x_d - x), segment-sum scatter, commit ----
__global__ void k_scatter(const float* __restrict__ x, const float* __restrict__ cb,
                          float* __restrict__ out) {
    int gt = blockIdx.x * blockDim.x + threadIdx.x;
    int t = gt >> 2, part = gt & 3;
    int idx = g_idx[t];
    const float4* xp = (const float4*)(x + (size_t)t * DIM + part * 16);
    const float4* cp = (const float4*)(cb + (size_t)idx * DIM + part * 16);
    float4* op = (float4*)(out + OFF_XOUT + (size_t)t * DIM + part * 16);
    float* sbm = &g_sumb[idx * DIM + part * 16];
    float cs = 0.0f;
#pragma unroll
    for (int q = 0; q < 4; q++) {
        float4 xv = xp[q];
        float4 cv = cp[q];
        float4 o;
        o.x = __fadd_rn(xv.x, __fsub_rn(cv.x, xv.x));
        o.y = __fadd_rn(xv.y, __fsub_rn(cv.y, xv.y));
        o.z = __fadd_rn(xv.z, __fsub_rn(cv.z, xv.z));
        o.w = __fadd_rn(xv.w, __fsub_rn(cv.w, xv.w));
        op[q] = o;
        float dx = __fsub_rn(xv.x, cv.x), dy = __fsub_rn(xv.y, cv.y);
        float dz = __fsub_rn(xv.z, cv.z), dw = __fsub_rn(xv.w, cv.w);
        cs += dx * dx + dy * dy + dz * dz + dw * dw;
        atomicAdd(sbm + q * 4 + 0, xv.x);
        atomicAdd(sbm + q * 4 + 1, xv.y);
        atomicAdd(sbm + q * 4 + 2, xv.z);
        atomicAdd(sbm + q * 4 + 3, xv.w);
    }
    if (part == 0) atomicAdd(&g_cntb[idx], 1.0f);
#pragma unroll
    for (int o = 16; o; o >>= 1) cs += __shfl_xor_sync(0xffffffff, cs, o);
    if ((threadIdx.x & 31) == 0) atomicAdd(&g_commit, cs);
}

// ---- K3: EMA update, new codebook, perplexity partials ----
__global__ void k_final(const float* __restrict__ x, const float* __restrict__ code_sum,
                        const float* __restrict__ code_count, float* __restrict__ out) {
    int i = blockIdx.x * 256 + threadIdx.x;
    int c = i >> 6, d = i & 63;
    float cntb = g_cntb[c];
    float ncnt = 0.99f * code_count[c] + 0.01f * cntb;
    float ns = 0.99f * code_sum[i] + 0.01f * g_sumb[i];
    out[OFF_NSUM + i] = ns;
    bool used = (ncnt >= 1.0f);
    float refreshed = ns / fmaxf(ncnt, 1e-8f);
    out[OFF_NCB + i] = used ? refreshed : x[i];
    if (d == 0) {
        out[OFF_NCNT + c] = ncnt;
        float p = cntb * (1.0f / 131072.0f);
        atomicAdd(&g_plog, p * logf(p + 1e-7f));
    }
}

// ---- K4: scalars ----
__global__ void k_scalars(float* __restrict__ out) {
    out[OFF_COMMIT] = g_commit * (1.0f / 8388608.0f);
    out[OFF_PERP]   = expf(-g_plog);
}

extern "C" void kernel_launch(void* const* d_in, const int* in_sizes, int n_in,
                              void* d_out, int out_size) {
    const float* x    = (const float*)d_in[0];
    const float* cb   = (const float*)d_in[1];
    const float* csum = (const float*)d_in[2];
    const float* ccnt = (const float*)d_in[3];
    float* out = (float*)d_out;

    cudaFuncSetAttribute(k1_hmma, cudaFuncAttributeMaxDynamicSharedMemorySize, SMEMT);

    k_zero<<<512, 256>>>();
    k_split_x<<<NTOK / 256, 256>>>(x);
    k_split_cb<<<8, 256>>>(cb);
    k1_hmma<<<NTOK / 128, 256, SMEMT>>>();
    k_scatter<<<NTOK * 4 / 256, 256>>>(x, cb, out);
    k_final<<<NCODE * DIM / 256, 256>>>(x, csum, ccnt, out);
    k_scalars<<<1, 1>>>(out);
}

// round 12
// speedup vs baseline: 2.4818x; 1.0424x over previous
#include <cuda_runtime.h>
#include <cuda_fp16.h>
#include <math.h>
#include <stdint.h>

#define NTOK   131072
#define NCODE  2048
#define DIM    64

// Output layout (tuple flattened):
#define OFF_XOUT   0
#define OFF_COMMIT 8388608
#define OFF_PERP   8388609
#define OFF_NCB    8388610
#define OFF_NSUM   8519682
#define OFF_NCNT   8650754

// ---- device scratch ----
__device__ int   g_idx[NTOK];
__device__ float g_cnorm[NCODE];
__device__ float g_sumb[NCODE * DIM];
__device__ float g_cntb[NCODE];
__device__ float g_commit;
__device__ float g_plog;
__device__ __half g_ch[NCODE * DIM];
__device__ __half g_cm[NCODE * DIM];

__device__ __forceinline__ uint32_t smem_u32(const void* p) {
    uint32_t a;
    asm("{ .reg .u64 t; cvta.to.shared.u64 t, %1; cvt.u32.u64 %0, t; }" : "=r"(a) : "l"(p));
    return a;
}
#define LDX4(r, addr) \
    asm volatile("ldmatrix.sync.aligned.m8n8.x4.shared.b16 {%0,%1,%2,%3}, [%4];" \
        : "=r"((r)[0]), "=r"((r)[1]), "=r"((r)[2]), "=r"((r)[3]) : "r"(addr))

__device__ __forceinline__ void mma16816(float* c, const uint32_t* a, uint32_t b0, uint32_t b1) {
    asm volatile("mma.sync.aligned.m16n8k16.row.col.f32.f16.f16.f32 "
        "{%0,%1,%2,%3},{%4,%5,%6,%7},{%8,%9},{%0,%1,%2,%3};"
        : "+f"(c[0]), "+f"(c[1]), "+f"(c[2]), "+f"(c[3])
        : "r"(a[0]), "r"(a[1]), "r"(a[2]), "r"(a[3]), "r"(b0), "r"(b1));
}
__device__ __forceinline__ void cpa16(uint32_t dst, const void* src) {
    asm volatile("cp.async.cg.shared.global [%0], [%1], 16;" :: "r"(dst), "l"(src));
}
#define CPA_COMMIT() asm volatile("cp.async.commit_group;" ::: "memory")
#define CPA_WAIT1()  asm volatile("cp.async.wait_group 1;" ::: "memory")

union U8H { __half h[8]; uint4 u; };
union U4H { __half h[4]; uint2 u; };

// smem buffer layout (bytes): bh[128*144] @0, bm[128*144] @18432, cns[128]f @36864
#define BUFB   37376
#define OFF_BM 18432
#define OFF_CN 36864
#define OFF_XN (2 * BUFB)          // xns[128] floats
#define SMEMT  (2 * BUFB + 512)

// ---- K0: zero accumulators ----
__global__ void k_zero() {
    int i = blockIdx.x * 256 + threadIdx.x;
    if (i < NCODE * DIM) g_sumb[i] = 0.0f;
    if (i < NCODE)       g_cntb[i] = 0.0f;
    if (i == 0) { g_commit = 0.0f; g_plog = 0.0f; }
}

// ---- K0b: split codebook into fp16 pair + ||c||^2 (reference rounding) ----
__global__ void k_split_cb(const float* __restrict__ cb) {
    int c = blockIdx.x * 256 + threadIdx.x;
    if (c >= NCODE) return;
    const float4* cp = (const float4*)(cb + (size_t)c * DIM);
    float cn = 0.0f;
#pragma unroll
    for (int q = 0; q < 8; q++) {
        float4 a = cp[2 * q], b = cp[2 * q + 1];
        float v[8] = {a.x, a.y, a.z, a.w, b.x, b.y, b.z, b.w};
        U8H H, M;
#pragma unroll
        for (int i = 0; i < 8; i++) {
            float vi = v[i];
            __half hb = __float2half_rn(vi);
            __half mb = __float2half_rn(__fsub_rn(vi, __half2float(hb)));
            H.h[i] = hb; M.h[i] = mb;
            cn = __fadd_rn(cn, __fmul_rn(vi, vi));
        }
        *(uint4*)&g_ch[(size_t)c * DIM + q * 8] = H.u;
        *(uint4*)&g_cm[(size_t)c * DIM + q * 8] = M.u;
    }
    g_cnorm[c] = cn;
}

// ---- K1: HMMA fp16-split distance GEMM + filtered fused argmin ----
// 3 passes (hh, hm, mh), cp.async double-buffered B chunks, x split in-kernel.
__device__ __forceinline__ void prefetch_chunk(uint32_t bsm, int n0, int tid) {
#pragma unroll
    for (int i = tid; i < 1024; i += 256) {
        int r = i >> 3, j = i & 7;
        cpa16(bsm + r * 144 + j * 16, &g_ch[(size_t)(n0 + r) * DIM + j * 8]);
        cpa16(bsm + OFF_BM + r * 144 + j * 16, &g_cm[(size_t)(n0 + r) * DIM + j * 8]);
    }
    if (tid < 32) cpa16(bsm + OFF_CN + tid * 16, &g_cnorm[n0 + tid * 4]);
}

__global__ void __launch_bounds__(256, 2) k1_hmma(const float* __restrict__ x) {
    extern __shared__ __align__(16) char dyn[];
    uint32_t sb = smem_u32(dyn);
    int tid = threadIdx.x, w = tid >> 5, l = tid & 31;
    int g = l >> 3, lr = l & 7, gid = l >> 2, tig = l & 3;
    int m0 = blockIdx.x * 128;
    float* xns = (float*)(dyn + OFF_XN);

    // in-kernel x split: fp32 -> (h, m) halves into buf0, ||x||^2 -> xns
    {
        int r = tid >> 1, seg = tid & 1;
        const float4* xp = (const float4*)(x + (size_t)(m0 + r) * DIM + seg * 32);
        float ps = 0.0f;
#pragma unroll
        for (int q = 0; q < 8; q++) {
            float4 v = xp[q];
            float vv[4] = {v.x, v.y, v.z, v.w};
            U4H H, M;
#pragma unroll
            for (int i = 0; i < 4; i++) {
                float vi = vv[i];
                __half hb = __float2half_rn(vi);
                __half mb = __float2half_rn(__fsub_rn(vi, __half2float(hb)));
                H.h[i] = hb; M.h[i] = mb;
                ps = __fadd_rn(ps, __fmul_rn(vi, vi));
            }
            int off = r * 144 + (seg * 32 + q * 4) * 2;
            *(uint2*)(dyn + off) = H.u;
            *(uint2*)(dyn + OFF_BM + off) = M.u;
        }
        float other = __shfl_xor_sync(0xffffffffu, ps, 1);
        float xnv = (seg == 0) ? __fadd_rn(ps, other) : __fadd_rn(other, ps);
        if (seg == 0) xns[r] = xnv;
    }
    __syncthreads();

    // A fragments register-resident for the whole kernel
    uint32_t ah[4][4], am[4][4];
    {
        int arow = w * 16 + (g & 1) * 8 + lr;
#pragma unroll
        for (int kk = 0; kk < 4; kk++) {
            int acol = kk * 16 + (g >> 1) * 8;
            LDX4(ah[kk], sb + arow * 144 + acol * 2);
            LDX4(am[kk], sb + OFF_BM + arow * 144 + acol * 2);
        }
    }
    float xn0 = xns[w * 16 + gid];
    float xn1 = xns[w * 16 + gid + 8];
    __syncthreads();

    float bv0 = 3.4e38f, bv1 = 3.4e38f;
    float thr0 = 3.4e38f, thr1 = 3.4e38f;
    int bi0 = 0, bi1 = 0;
    const float EPS = 1e-3f;

    prefetch_chunk(sb, 0, tid);          CPA_COMMIT();
    prefetch_chunk(sb + BUFB, 128, tid); CPA_COMMIT();

    for (int c = 0; c < 16; c++) {
        uint32_t bb = sb + (c & 1) * BUFB;
        const float* cns = (const float*)(dyn + (c & 1) * BUFB + OFF_CN);
        CPA_WAIT1();
        __syncthreads();

#pragma unroll
        for (int hf = 0; hf < 2; hf++) {
            float acc[8][4];
#pragma unroll
            for (int n = 0; n < 8; n++)
#pragma unroll
                for (int q = 0; q < 4; q++) acc[n][q] = 0.0f;

#pragma unroll
            for (int kk = 0; kk < 4; kk++) {
#pragma unroll
                for (int p = 0; p < 4; p++) {
                    int brow = hf * 64 + p * 16 + (g & 1) * 8 + lr;
                    int bcol = kk * 16 + (g >> 1) * 8;
                    uint32_t bh[4], bm[4];
                    LDX4(bh, bb + brow * 144 + bcol * 2);
                    LDX4(bm, bb + OFF_BM + brow * 144 + bcol * 2);
                    mma16816(acc[2 * p],     ah[kk], bh[0], bh[2]);
                    mma16816(acc[2 * p],     ah[kk], bm[0], bm[2]);
                    mma16816(acc[2 * p],     am[kk], bh[0], bh[2]);
                    mma16816(acc[2 * p + 1], ah[kk], bh[1], bh[3]);
                    mma16816(acc[2 * p + 1], ah[kk], bm[1], bm[3]);
                    mma16816(acc[2 * p + 1], am[kk], bh[1], bh[3]);
                }
            }
            // Filtered epilogue. Fast path: t = fma(-2,dot,cn) vs thr = bv-xn+EPS.
            // Skip is provably safe (s >= xn + t - 1e-5 > bv when t >= thr).
            // Slow path: exact reference-order scores, ascending index, strict <.
#pragma unroll
            for (int nt = 0; nt < 8; nt++) {
                int nl = hf * 64 + nt * 8 + 2 * tig;
                float cn0 = cns[nl], cn1 = cns[nl + 1];
                int ci = c * 128 + nl;
                float t0 = __fmaf_rn(-2.0f, acc[nt][0], cn0);
                float t1 = __fmaf_rn(-2.0f, acc[nt][1], cn1);
                float t2 = __fmaf_rn(-2.0f, acc[nt][2], cn0);
                float t3 = __fmaf_rn(-2.0f, acc[nt][3], cn1);
                bool p = (t0 < thr0) | (t1 < thr0) | (t2 < thr1) | (t3 < thr1);
                if (__any_sync(0xffffffffu, p)) {
                    float s;
                    s = __fadd_rn(__fsub_rn(xn0, __fmul_rn(2.0f, acc[nt][0])), cn0);
                    if (s < bv0) { bv0 = s; bi0 = ci; }
                    s = __fadd_rn(__fsub_rn(xn0, __fmul_rn(2.0f, acc[nt][1])), cn1);
                    if (s < bv0) { bv0 = s; bi0 = ci + 1; }
                    s = __fadd_rn(__fsub_rn(xn1, __fmul_rn(2.0f, acc[nt][2])), cn0);
                    if (s < bv1) { bv1 = s; bi1 = ci; }
                    s = __fadd_rn(__fsub_rn(xn1, __fmul_rn(2.0f, acc[nt][3])), cn1);
                    if (s < bv1) { bv1 = s; bi1 = ci + 1; }
                    thr0 = __fadd_rn(__fsub_rn(bv0, xn0), EPS);
                    thr1 = __fadd_rn(__fsub_rn(bv1, xn1), EPS);
                }
            }
        }
        __syncthreads();
        if (c + 2 < 16) prefetch_chunk(bb, (c + 2) * 128, tid);
        CPA_COMMIT();
    }

    // quad (4-lane) reduce, tie -> lower index
#pragma unroll
    for (int off = 1; off <= 2; off <<= 1) {
        float ov0 = __shfl_xor_sync(0xffffffffu, bv0, off);
        int   oi0 = __shfl_xor_sync(0xffffffffu, bi0, off);
        if (ov0 < bv0 || (ov0 == bv0 && oi0 < bi0)) { bv0 = ov0; bi0 = oi0; }
        float ov1 = __shfl_xor_sync(0xffffffffu, bv1, off);
        int   oi1 = __shfl_xor_sync(0xffffffffu, bi1, off);
        if (ov1 < bv1 || (ov1 == bv1 && oi1 < bi1)) { bv1 = ov1; bi1 = oi1; }
    }
    if (tig == 0) {
        g_idx[m0 + w * 16 + gid]     = bi0;
        g_idx[m0 + w * 16 + gid + 8] = bi1;
    }
}

// ---- K2: gather x_d, x_out = x + (x_d - x), segment-sum scatter, commit ----
__global__ void k_scatter(const float* __restrict__ x, const float* __restrict__ cb,
                          float* __restrict__ out) {
    int gt = blockIdx.x * blockDim.x + threadIdx.x;
    int t = gt >> 2, part = gt & 3;
    int idx = g_idx[t];
    const float4* xp = (const float4*)(x + (size_t)t * DIM + part * 16);
    const float4* cp = (const float4*)(cb + (size_t)idx * DIM + part * 16);
    float4* op = (float4*)(out + OFF_XOUT + (size_t)t * DIM + part * 16);
    float* sbm = &g_sumb[idx * DIM + part * 16];
    float cs = 0.0f;
#pragma unroll
    for (int q = 0; q < 4; q++) {
        float4 xv = xp[q];
        float4 cv = cp[q];
        float4 o;
        o.x = __fadd_rn(xv.x, __fsub_rn(cv.x, xv.x));
        o.y = __fadd_rn(xv.y, __fsub_rn(cv.y, xv.y));
        o.z = __fadd_rn(xv.z, __fsub_rn(cv.z, xv.z));
        o.w = __fadd_rn(xv.w, __fsub_rn(cv.w, xv.w));
        op[q] = o;
        float dx = __fsub_rn(xv.x, cv.x), dy = __fsub_rn(xv.y, cv.y);
        float dz = __fsub_rn(xv.z, cv.z), dw = __fsub_rn(xv.w, cv.w);
        cs += dx * dx + dy * dy + dz * dz + dw * dw;
        atomicAdd(sbm + q * 4 + 0, xv.x);
        atomicAdd(sbm + q * 4 + 1, xv.y);
        atomicAdd(sbm + q * 4 + 2, xv.z);
        atomicAdd(sbm + q * 4 + 3, xv.w);
    }
    if (part == 0) atomicAdd(&g_cntb[idx], 1.0f);
#pragma unroll
    for (int o = 16; o; o >>= 1) cs += __shfl_xor_sync(0xffffffff, cs, o);
    if ((threadIdx.x & 31) == 0) atomicAdd(&g_commit, cs);
}

// ---- K3: EMA update, new codebook, perplexity partials ----
__global__ void k_final(const float* __restrict__ x, const float* __restrict__ code_sum,
                        const float* __restrict__ code_count, float* __restrict__ out) {
    int i = blockIdx.x * 256 + threadIdx.x;
    int c = i >> 6, d = i & 63;
    float cntb = g_cntb[c];
    float ncnt = 0.99f * code_count[c] + 0.01f * cntb;
    float ns = 0.99f * code_sum[i] + 0.01f * g_sumb[i];
    out[OFF_NSUM + i] = ns;
    bool used = (ncnt >= 1.0f);
    float refreshed = ns / fmaxf(ncnt, 1e-8f);
    out[OFF_NCB + i] = used ? refreshed : x[i];
    if (d == 0) {
        out[OFF_NCNT + c] = ncnt;
        float p = cntb * (1.0f / 131072.0f);
        atomicAdd(&g_plog, p * logf(p + 1e-7f));
    }
}

// ---- K4: scalars ----
__global__ void k_scalars(float* __restrict__ out) {
    out[OFF_COMMIT] = g_commit * (1.0f / 8388608.0f);
    out[OFF_PERP]   = expf(-g_plog);
}

extern "C" void kernel_launch(void* const* d_in, const int* in_sizes, int n_in,
                              void* d_out, int out_size) {
    const float* x    = (const float*)d_in[0];
    const float* cb   = (const float*)d_in[1];
    const float* csum = (const float*)d_in[2];
    const float* ccnt = (const float*)d_in[3];
    float* out = (float*)d_out;

    cudaFuncSetAttribute(k1_hmma, cudaFuncAttributeMaxDynamicSharedMemorySize, SMEMT);

    k_zero<<<512, 256>>>();
    k_split_cb<<<8, 256>>>(cb);
    k1_hmma<<<NTOK / 128, 256, SMEMT>>>(x);
    k_scatter<<<NTOK * 4 / 256, 256>>>(x, cb, out);
    k_final<<<NCODE * DIM / 256, 256>>>(x, csum, ccnt, out);
    k_scalars<<<1, 1>>>(out);
}